// round 5
// baseline (speedup 1.0000x reference)
#include <cuda_runtime.h>
#include <cuda_bf16.h>
#include <mma.h>

using namespace nvcuda;

// Problem constants
#define S_DIM 8192
#define X_DIM 512
#define Q_DIM 512
#define ZV_DIM 512
#define H_DIM 8

// Scratch (device globals: allocation-free)
__device__ float g_k[512 * 512];
__device__ float g_v[512 * 512];
__device__ float g_bufA[(size_t)H_DIM * S_DIM * 512];  // q, then z
__device__ float g_bufB[(size_t)H_DIM * S_DIM * 512];  // e (logits -> softmax)

// ---------------- GEMM: tf32 wmma, 128x128x32 tile, 8 warps (4x2) ----------------
constexpr int BM = 128, BN = 128, BK = 32;
constexpr int LDA_S = BK + 8;    // 40  : As[BM][LDA_S]
constexpr int LDBT_S = BK + 8;   // 40  : Bst[BN][LDBT_S]  (B transposed: (k,n) at n*ldb+k)
constexpr int LDBN_S = BN + 8;   // 136 : Bs[BK][LDBN_S]   (B normal: (k,n) at k*ldb+n)
constexpr int LDC_S = BN + 8;    // 136 : Cs[BM][LDC_S]
constexpr int GEMM_SMEM_BYTES = BM * LDC_S * 4;  // 69632 (Cs is the max; aliases As+Bs)

template <bool BTRANS, bool AHEADED, bool ATOMIC>
__global__ __launch_bounds__(256)
void gemm_tf32_kernel(const float* __restrict__ A, const float* __restrict__ B,
                      float* __restrict__ C, const float* __restrict__ bias,
                      float alpha, int M, int N, int K,
                      int lda, int ldb, int ldc,
                      long long strideA, long long strideB, long long strideC,
                      long long strideBias, long long headSlab) {
    extern __shared__ float smem[];
    float* As = smem;                      // [BM][LDA_S]
    float* Bs = smem + BM * LDA_S;         // trans: [BN][LDBT_S] ; normal: [BK][LDBN_S]
    float* Cs = smem;                      // [BM][LDC_S] (reused after mainloop)

    const int z = blockIdx.z;
    int kBegin = 0, kCount = K;
    if constexpr (ATOMIC) {
        kCount = K / gridDim.z;
        kBegin = z * kCount;
    } else {
        A += z * strideA;
        B += z * strideB;
        C += z * strideC;
        if (bias) bias += z * strideBias;
    }
    const int mBase = blockIdx.y * BM;
    const int nBase = blockIdx.x * BN;

    const int tid = threadIdx.x;
    const int warp = tid >> 5;
    const int wm = warp >> 1;  // 0..3  (32-row strip)
    const int wn = warp & 1;   // 0..1  (64-col strip)

    wmma::fragment<wmma::accumulator, 16, 16, 8, float> acc[2][4];
#pragma unroll
    for (int i = 0; i < 2; ++i)
#pragma unroll
        for (int j = 0; j < 4; ++j) wmma::fill_fragment(acc[i][j], 0.0f);

    const int nChunks = kCount / BK;
    for (int kc = 0; kc < nChunks; ++kc) {
        const int kcol = kBegin + kc * BK;

        // ---- load A tile [BM x BK] ----
#pragma unroll
        for (int it = 0; it < 4; ++it) {
            const int idx = tid + it * 256;  // 0..1023
            const int r = idx >> 3;          // 0..127
            const int c4 = idx & 7;          // float4 index within 32-col row
            const float* src;
            if constexpr (AHEADED) {
                src = A + (long long)(kcol >> 9) * headSlab +
                      (long long)(mBase + r) * 512 + (kcol & 511) + c4 * 4;
            } else {
                src = A + (long long)(mBase + r) * lda + kcol + c4 * 4;
            }
            *reinterpret_cast<float4*>(&As[r * LDA_S + c4 * 4]) =
                *reinterpret_cast<const float4*>(src);
        }
        // ---- load B tile ----
        if constexpr (BTRANS) {
#pragma unroll
            for (int it = 0; it < 4; ++it) {
                const int idx = tid + it * 256;
                const int n = idx >> 3;
                const int c4 = idx & 7;
                const float* src = B + (long long)(nBase + n) * ldb + kcol + c4 * 4;
                *reinterpret_cast<float4*>(&Bs[n * LDBT_S + c4 * 4]) =
                    *reinterpret_cast<const float4*>(src);
            }
        } else {
#pragma unroll
            for (int it = 0; it < 4; ++it) {
                const int idx = tid + it * 256;
                const int r = idx >> 5;   // k-row 0..31
                const int c4 = idx & 31;  // n/4
                const float* src = B + (long long)(kcol + r) * ldb + nBase + c4 * 4;
                *reinterpret_cast<float4*>(&Bs[r * LDBN_S + c4 * 4]) =
                    *reinterpret_cast<const float4*>(src);
            }
        }
        __syncthreads();

        // ---- mma ----
#pragma unroll
        for (int kk = 0; kk < BK / 8; ++kk) {
            wmma::fragment<wmma::matrix_a, 16, 16, 8, wmma::precision::tf32,
                           wmma::row_major> af[2];
#pragma unroll
            for (int i = 0; i < 2; ++i) {
                wmma::load_matrix_sync(af[i], &As[(wm * 32 + i * 16) * LDA_S + kk * 8],
                                       LDA_S);
#pragma unroll
                for (int t = 0; t < af[i].num_elements; ++t)
                    af[i].x[t] = wmma::__float_to_tf32(af[i].x[t]);
            }
#pragma unroll
            for (int j = 0; j < 4; ++j) {
                if constexpr (BTRANS) {
                    wmma::fragment<wmma::matrix_b, 16, 16, 8, wmma::precision::tf32,
                                   wmma::col_major> bf;
                    wmma::load_matrix_sync(
                        bf, &Bs[(wn * 64 + j * 16) * LDBT_S + kk * 8], LDBT_S);
#pragma unroll
                    for (int t = 0; t < bf.num_elements; ++t)
                        bf.x[t] = wmma::__float_to_tf32(bf.x[t]);
#pragma unroll
                    for (int i = 0; i < 2; ++i)
                        wmma::mma_sync(acc[i][j], af[i], bf, acc[i][j]);
                } else {
                    wmma::fragment<wmma::matrix_b, 16, 16, 8, wmma::precision::tf32,
                                   wmma::row_major> bf;
                    wmma::load_matrix_sync(
                        bf, &Bs[(kk * 8) * LDBN_S + wn * 64 + j * 16], LDBN_S);
#pragma unroll
                    for (int t = 0; t < bf.num_elements; ++t)
                        bf.x[t] = wmma::__float_to_tf32(bf.x[t]);
#pragma unroll
                    for (int i = 0; i < 2; ++i)
                        wmma::mma_sync(acc[i][j], af[i], bf, acc[i][j]);
                }
            }
        }
        __syncthreads();
    }

    // ---- epilogue via smem for coalesced + per-column bias ----
#pragma unroll
    for (int i = 0; i < 2; ++i)
#pragma unroll
        for (int j = 0; j < 4; ++j)
            wmma::store_matrix_sync(&Cs[(wm * 32 + i * 16) * LDC_S + wn * 64 + j * 16],
                                    acc[i][j], LDC_S, wmma::mem_row_major);
    __syncthreads();

#pragma unroll
    for (int it = 0; it < 16; ++it) {
        const int idx = tid + it * 256;  // 0..4095
        const int r = idx >> 5;          // 0..127
        const int c4 = idx & 31;         // 0..31
        float4 v = *reinterpret_cast<float4*>(&Cs[r * LDC_S + c4 * 4]);
        const int ncol = nBase + c4 * 4;
        float* dst = C + (long long)(mBase + r) * ldc + ncol;
        if constexpr (ATOMIC) {
            atomicAdd(dst + 0, v.x);
            atomicAdd(dst + 1, v.y);
            atomicAdd(dst + 2, v.z);
            atomicAdd(dst + 3, v.w);
        } else {
            if (bias != nullptr) {
                v.x += bias[ncol + 0];
                v.y += bias[ncol + 1];
                v.z += bias[ncol + 2];
                v.w += bias[ncol + 3];
            }
            v.x *= alpha; v.y *= alpha; v.z *= alpha; v.w *= alpha;
            *reinterpret_cast<float4*>(dst) = v;
        }
    }
}

// ---------------- softmax over rows of 512 (1 warp per row) ----------------
__global__ void softmax512_kernel(float* __restrict__ data, int rows) {
    const int row = blockIdx.x * blockDim.y + threadIdx.y;
    if (row >= rows) return;
    float* p = data + (long long)row * 512;
    const int lane = threadIdx.x;
    float4 v[4];
    float mx = -3.0e38f;
#pragma unroll
    for (int i = 0; i < 4; ++i) {
        v[i] = reinterpret_cast<float4*>(p)[lane + i * 32];
        mx = fmaxf(mx, fmaxf(fmaxf(v[i].x, v[i].y), fmaxf(v[i].z, v[i].w)));
    }
#pragma unroll
    for (int o = 16; o; o >>= 1) mx = fmaxf(mx, __shfl_xor_sync(0xffffffffu, mx, o));
    float sum = 0.0f;
#pragma unroll
    for (int i = 0; i < 4; ++i) {
        v[i].x = __expf(v[i].x - mx);
        v[i].y = __expf(v[i].y - mx);
        v[i].z = __expf(v[i].z - mx);
        v[i].w = __expf(v[i].w - mx);
        sum += v[i].x + v[i].y + v[i].z + v[i].w;
    }
#pragma unroll
    for (int o = 16; o; o >>= 1) sum += __shfl_xor_sync(0xffffffffu, sum, o);
    const float inv = 1.0f / sum;
#pragma unroll
    for (int i = 0; i < 4; ++i) {
        v[i].x *= inv; v[i].y *= inv; v[i].z *= inv; v[i].w *= inv;
        reinterpret_cast<float4*>(p)[lane + i * 32] = v[i];
    }
}

__global__ void zero_kernel(float* __restrict__ p, int n) {
    const int i = blockIdx.x * blockDim.x + threadIdx.x;
    if (i < n) p[i] = 0.0f;
}

// ---------------- launcher ----------------
extern "C" void kernel_launch(void* const* d_in, const int* in_sizes, int n_in,
                              void* d_out, int out_size) {
    const float* x    = (const float*)d_in[0];  // [S, X]
    const float* enc0 = (const float*)d_in[1];  // [Q, S]
    const float* enc1 = (const float*)d_in[2];  // [ZV, S]
    const float* Wq   = (const float*)d_in[3];  // [H, Q, X]
    const float* bq   = (const float*)d_in[4];  // [H, Q]
    const float* Wc   = (const float*)d_in[5];  // [ZV, H*ZV]
    const float* bc   = (const float*)d_in[6];  // [ZV]
    float* out = (float*)d_out;                 // [S, ZV]

    float *kbuf, *vbuf, *bufA, *bufB;
    cudaGetSymbolAddress((void**)&kbuf, g_k);
    cudaGetSymbolAddress((void**)&vbuf, g_v);
    cudaGetSymbolAddress((void**)&bufA, g_bufA);
    cudaGetSymbolAddress((void**)&bufB, g_bufB);

    cudaFuncSetAttribute(gemm_tf32_kernel<false, false, true>,
                         cudaFuncAttributeMaxDynamicSharedMemorySize, GEMM_SMEM_BYTES);
    cudaFuncSetAttribute(gemm_tf32_kernel<true, false, false>,
                         cudaFuncAttributeMaxDynamicSharedMemorySize, GEMM_SMEM_BYTES);
    cudaFuncSetAttribute(gemm_tf32_kernel<true, true, false>,
                         cudaFuncAttributeMaxDynamicSharedMemorySize, GEMM_SMEM_BYTES);

    const long long headSlab = (long long)S_DIM * 512;
    const float invSqrtQ = 0.044194173824159216f;  // 1/sqrt(512)

    // zero k, v (split-K atomics accumulate into them)
    zero_kernel<<<(512 * 512 + 255) / 256, 256>>>(kbuf, 512 * 512);
    zero_kernel<<<(512 * 512 + 255) / 256, 256>>>(vbuf, 512 * 512);

    // k = enc0 @ x ; v = enc1 @ x   (M=N=512, K=8192, split-K=16)
    {
        dim3 g(512 / BN, 512 / BM, 16);
        gemm_tf32_kernel<false, false, true><<<g, 256, GEMM_SMEM_BYTES>>>(
            enc0, x, kbuf, nullptr, 1.0f, 512, 512, 8192, 8192, 512, 512,
            0, 0, 0, 0, 0);
        gemm_tf32_kernel<false, false, true><<<g, 256, GEMM_SMEM_BYTES>>>(
            enc1, x, vbuf, nullptr, 1.0f, 512, 512, 8192, 8192, 512, 512,
            0, 0, 0, 0, 0);
    }

    dim3 gbig(512 / BN, S_DIM / BM, H_DIM);  // (4, 64, 8)

    // q' = (x @ Wq[h]^T + bq[h]) * 1/sqrt(Q)  -> bufA
    gemm_tf32_kernel<true, false, false><<<gbig, 256, GEMM_SMEM_BYTES>>>(
        x, Wq, bufA, bq, invSqrtQ, S_DIM, 512, 512, 512, 512, 512,
        0, 512LL * 512, headSlab, 512, 0);

    // e = q' @ k^T  -> bufB
    gemm_tf32_kernel<true, false, false><<<gbig, 256, GEMM_SMEM_BYTES>>>(
        bufA, kbuf, bufB, nullptr, 1.0f, S_DIM, 512, 512, 512, 512, 512,
        headSlab, 0, headSlab, 0, 0);

    // softmax rows (H*S rows of 512), in place
    softmax512_kernel<<<(H_DIM * S_DIM) / 8, dim3(32, 8)>>>(bufB, H_DIM * S_DIM);

    // z = e @ v^T  -> bufA
    gemm_tf32_kernel<true, false, false><<<gbig, 256, GEMM_SMEM_BYTES>>>(
        bufB, vbuf, bufA, nullptr, 1.0f, S_DIM, 512, 512, 512, 512, 512,
        headSlab, 0, headSlab, 0, 0);

    // out = super_z @ Wc^T + bc   (A head-interleaved: col c -> z[c>>9][s][c&511])
    {
        dim3 g(512 / BN, S_DIM / BM, 1);
        gemm_tf32_kernel<true, true, false><<<g, 256, GEMM_SMEM_BYTES>>>(
            bufA, Wc, out, bc, 1.0f, S_DIM, 512, H_DIM * 512, 512, H_DIM * 512, 512,
            0, 0, 0, 0, headSlab);
    }
}

// round 7
// speedup vs baseline: 1.0546x; 1.0546x over previous
#include <cuda_runtime.h>
#include <cuda_bf16.h>
#include <mma.h>
#include <cstdint>

using namespace nvcuda;

// Problem constants
#define S_DIM 8192
#define X_DIM 512
#define Q_DIM 512
#define ZV_DIM 512
#define H_DIM 8

// Scratch (device globals: allocation-free)
__device__ float g_k[512 * 512];
__device__ float g_v[512 * 512];
__device__ float g_bufA[(size_t)H_DIM * S_DIM * 512];  // q, then z
__device__ float g_bufB[(size_t)H_DIM * S_DIM * 512];  // e (logits -> softmax)
// tf32-pre-rounded copies of the inputs
__device__ float g_xr[(size_t)S_DIM * X_DIM];
__device__ float g_e0r[(size_t)Q_DIM * S_DIM];
__device__ float g_e1r[(size_t)ZV_DIM * S_DIM];
__device__ float g_wqr[(size_t)H_DIM * Q_DIM * X_DIM];
__device__ float g_wcr[(size_t)ZV_DIM * H_DIM * ZV_DIM];

// ---------------- cp.async helpers ----------------
__device__ __forceinline__ void cp_async16(void* smem_ptr, const void* gptr) {
    unsigned int saddr = (unsigned int)__cvta_generic_to_shared(smem_ptr);
    asm volatile("cp.async.cg.shared.global [%0], [%1], 16;\n" ::"r"(saddr), "l"(gptr));
}
__device__ __forceinline__ void cp_commit() {
    asm volatile("cp.async.commit_group;\n" ::);
}
template <int N>
__device__ __forceinline__ void cp_wait() {
    asm volatile("cp.async.wait_group %0;\n" ::"n"(N));
}

// ---------------- GEMM: tf32 wmma, 128x128x32 tile, 8 warps (4x2), 2-stage cp.async ----
constexpr int BM = 128, BN = 128, BK = 32;
constexpr int LDA_S = BK + 8;    // 40  : As[BM][LDA_S]
constexpr int LDBT_S = BK + 8;   // 40  : Bst[BN][LDBT_S]  (B transposed: (k,n) at n*ldb+k)
constexpr int LDBN_S = BN + 8;   // 136 : Bs[BK][LDBN_S]   (B normal: (k,n) at k*ldb+n)
constexpr int LDC_S = BN + 8;    // 136 : Cs[BM][LDC_S]
constexpr int STAGE_F = BM * LDA_S + BN * LDBT_S;  // 10240 floats = 40960 B per stage
constexpr int GEMM_SMEM_BYTES = 2 * STAGE_F * 4;   // 81920 (>= epilogue Cs 69632)

template <bool BTRANS, bool AHEADED, bool ATOMIC, bool ROUND>
__global__ __launch_bounds__(256)
void gemm_tf32_kernel(const float* __restrict__ A, const float* __restrict__ B,
                      float* __restrict__ C, const float* __restrict__ bias,
                      float alpha, int M, int N, int K,
                      int lda, int ldb, int ldc,
                      long long strideA, long long strideB, long long strideC,
                      long long strideBias, long long headSlab) {
    extern __shared__ float smem[];

    const int z = blockIdx.z;
    int kBegin = 0, kCount = K;
    if constexpr (ATOMIC) {
        kCount = K / gridDim.z;
        kBegin = z * kCount;
    } else {
        A += z * strideA;
        B += z * strideB;
        C += z * strideC;
        if (bias) bias += z * strideBias;
    }
    const int mBase = blockIdx.y * BM;
    const int nBase = blockIdx.x * BN;

    const int tid = threadIdx.x;
    const int warp = tid >> 5;
    const int wm = warp >> 1;  // 0..3  (32-row strip)
    const int wn = warp & 1;   // 0..1  (64-col strip)

    wmma::fragment<wmma::accumulator, 16, 16, 8, float> acc[2][4];
#pragma unroll
    for (int i = 0; i < 2; ++i)
#pragma unroll
        for (int j = 0; j < 4; ++j) wmma::fill_fragment(acc[i][j], 0.0f);

    // ---- async stage loader ----
    auto load_stage = [&](int kc, int stage) {
        float* As = smem + stage * STAGE_F;
        float* Bs = As + BM * LDA_S;
        const int kcol = kBegin + kc * BK;
#pragma unroll
        for (int it = 0; it < 4; ++it) {
            const int idx = tid + it * 256;  // 0..1023
            const int r = idx >> 3;          // 0..127
            const int c4 = idx & 7;          // float4 index in 32-col row
            const float* src;
            if constexpr (AHEADED) {
                src = A + (long long)(kcol >> 9) * headSlab +
                      (long long)(mBase + r) * 512 + (kcol & 511) + c4 * 4;
            } else {
                src = A + (long long)(mBase + r) * lda + kcol + c4 * 4;
            }
            cp_async16(&As[r * LDA_S + c4 * 4], src);
        }
        if constexpr (BTRANS) {
#pragma unroll
            for (int it = 0; it < 4; ++it) {
                const int idx = tid + it * 256;
                const int n = idx >> 3;
                const int c4 = idx & 7;
                cp_async16(&Bs[n * LDBT_S + c4 * 4],
                           B + (long long)(nBase + n) * ldb + kcol + c4 * 4);
            }
        } else {
#pragma unroll
            for (int it = 0; it < 4; ++it) {
                const int idx = tid + it * 256;
                const int r = idx >> 5;   // k-row 0..31
                const int c4 = idx & 31;  // n/4
                cp_async16(&Bs[r * LDBN_S + c4 * 4],
                           B + (long long)(kcol + r) * ldb + nBase + c4 * 4);
            }
        }
    };

    const int nChunks = kCount / BK;

    // prologue: stage 0 in flight
    load_stage(0, 0);
    cp_commit();

    for (int kc = 0; kc < nChunks; ++kc) {
        cp_wait<0>();
        __syncthreads();
        // issue next stage (overwrites buffer last computed at kc-1; sync above covers it)
        if (kc + 1 < nChunks) {
            load_stage(kc + 1, (kc + 1) & 1);
            cp_commit();
        }
        const float* As = smem + (kc & 1) * STAGE_F;
        const float* Bs = As + BM * LDA_S;

#pragma unroll
        for (int kk = 0; kk < BK / 8; ++kk) {
            wmma::fragment<wmma::matrix_a, 16, 16, 8, wmma::precision::tf32,
                           wmma::row_major> af[2];
#pragma unroll
            for (int i = 0; i < 2; ++i)
                wmma::load_matrix_sync(af[i], &As[(wm * 32 + i * 16) * LDA_S + kk * 8],
                                       LDA_S);
#pragma unroll
            for (int j = 0; j < 4; ++j) {
                if constexpr (BTRANS) {
                    wmma::fragment<wmma::matrix_b, 16, 16, 8, wmma::precision::tf32,
                                   wmma::col_major> bf;
                    wmma::load_matrix_sync(
                        bf, &Bs[(wn * 64 + j * 16) * LDBT_S + kk * 8], LDBT_S);
#pragma unroll
                    for (int i = 0; i < 2; ++i)
                        wmma::mma_sync(acc[i][j], af[i], bf, acc[i][j]);
                } else {
                    wmma::fragment<wmma::matrix_b, 16, 16, 8, wmma::precision::tf32,
                                   wmma::row_major> bf;
                    wmma::load_matrix_sync(
                        bf, &Bs[(kk * 8) * LDBN_S + wn * 64 + j * 16], LDBN_S);
#pragma unroll
                    for (int i = 0; i < 2; ++i)
                        wmma::mma_sync(acc[i][j], af[i], bf, acc[i][j]);
                }
            }
        }
    }
    __syncthreads();  // stage buffers now free for epilogue reuse

    // ---- epilogue via smem for coalesced stores + per-column bias ----
    float* Cs = smem;  // [BM][LDC_S]
#pragma unroll
    for (int i = 0; i < 2; ++i)
#pragma unroll
        for (int j = 0; j < 4; ++j)
            wmma::store_matrix_sync(&Cs[(wm * 32 + i * 16) * LDC_S + wn * 64 + j * 16],
                                    acc[i][j], LDC_S, wmma::mem_row_major);
    __syncthreads();

#pragma unroll
    for (int it = 0; it < 16; ++it) {
        const int idx = tid + it * 256;  // 0..4095
        const int r = idx >> 5;          // 0..127
        const int c4 = idx & 31;         // 0..31
        float4 v = *reinterpret_cast<float4*>(&Cs[r * LDC_S + c4 * 4]);
        const int ncol = nBase + c4 * 4;
        float* dst = C + (long long)(mBase + r) * ldc + ncol;
        if constexpr (ATOMIC) {
            atomicAdd(dst + 0, v.x);
            atomicAdd(dst + 1, v.y);
            atomicAdd(dst + 2, v.z);
            atomicAdd(dst + 3, v.w);
        } else {
            if (bias != nullptr) {
                v.x += bias[ncol + 0];
                v.y += bias[ncol + 1];
                v.z += bias[ncol + 2];
                v.w += bias[ncol + 3];
            }
            v.x *= alpha; v.y *= alpha; v.z *= alpha; v.w *= alpha;
            if constexpr (ROUND) {
                v.x = wmma::__float_to_tf32(v.x);
                v.y = wmma::__float_to_tf32(v.y);
                v.z = wmma::__float_to_tf32(v.z);
                v.w = wmma::__float_to_tf32(v.w);
            }
            *reinterpret_cast<float4*>(dst) = v;
        }
    }
}

// ---------------- softmax over rows of 512 (1 warp per row), tf32-rounded output ------
__global__ void softmax512_kernel(float* __restrict__ data, int rows) {
    const int row = blockIdx.x * blockDim.y + threadIdx.y;
    if (row >= rows) return;
    float* p = data + (long long)row * 512;
    const int lane = threadIdx.x;
    float4 v[4];
    float mx = -3.0e38f;
#pragma unroll
    for (int i = 0; i < 4; ++i) {
        v[i] = reinterpret_cast<float4*>(p)[lane + i * 32];
        mx = fmaxf(mx, fmaxf(fmaxf(v[i].x, v[i].y), fmaxf(v[i].z, v[i].w)));
    }
#pragma unroll
    for (int o = 16; o; o >>= 1) mx = fmaxf(mx, __shfl_xor_sync(0xffffffffu, mx, o));
    float sum = 0.0f;
#pragma unroll
    for (int i = 0; i < 4; ++i) {
        v[i].x = __expf(v[i].x - mx);
        v[i].y = __expf(v[i].y - mx);
        v[i].z = __expf(v[i].z - mx);
        v[i].w = __expf(v[i].w - mx);
        sum += v[i].x + v[i].y + v[i].z + v[i].w;
    }
#pragma unroll
    for (int o = 16; o; o >>= 1) sum += __shfl_xor_sync(0xffffffffu, sum, o);
    const float inv = 1.0f / sum;
#pragma unroll
    for (int i = 0; i < 4; ++i) {
        v[i].x = wmma::__float_to_tf32(v[i].x * inv);
        v[i].y = wmma::__float_to_tf32(v[i].y * inv);
        v[i].z = wmma::__float_to_tf32(v[i].z * inv);
        v[i].w = wmma::__float_to_tf32(v[i].w * inv);
        reinterpret_cast<float4*>(p)[lane + i * 32] = v[i];
    }
}

__global__ void zero_kernel(float* __restrict__ p, int n) {
    const int i = blockIdx.x * blockDim.x + threadIdx.x;
    if (i < n) p[i] = 0.0f;
}

// round-copy (or in-place round when in == out), vectorized
__global__ void round_tf32_kernel(const float* __restrict__ in, float* __restrict__ out,
                                  int n4) {
    const int i = blockIdx.x * blockDim.x + threadIdx.x;
    if (i < n4) {
        float4 v = reinterpret_cast<const float4*>(in)[i];
        v.x = wmma::__float_to_tf32(v.x);
        v.y = wmma::__float_to_tf32(v.y);
        v.z = wmma::__float_to_tf32(v.z);
        v.w = wmma::__float_to_tf32(v.w);
        reinterpret_cast<float4*>(out)[i] = v;
    }
}

// ---------------- launcher ----------------
extern "C" void kernel_launch(void* const* d_in, const int* in_sizes, int n_in,
                              void* d_out, int out_size) {
    const float* x    = (const float*)d_in[0];  // [S, X]
    const float* enc0 = (const float*)d_in[1];  // [Q, S]
    const float* enc1 = (const float*)d_in[2];  // [ZV, S]
    const float* Wq   = (const float*)d_in[3];  // [H, Q, X]
    const float* bq   = (const float*)d_in[4];  // [H, Q]
    const float* Wc   = (const float*)d_in[5];  // [ZV, H*ZV]
    const float* bc   = (const float*)d_in[6];  // [ZV]
    float* out = (float*)d_out;                 // [S, ZV]

    float *kbuf, *vbuf, *bufA, *bufB, *xr, *e0r, *e1r, *wqr, *wcr;
    cudaGetSymbolAddress((void**)&kbuf, g_k);
    cudaGetSymbolAddress((void**)&vbuf, g_v);
    cudaGetSymbolAddress((void**)&bufA, g_bufA);
    cudaGetSymbolAddress((void**)&bufB, g_bufB);
    cudaGetSymbolAddress((void**)&xr, g_xr);
    cudaGetSymbolAddress((void**)&e0r, g_e0r);
    cudaGetSymbolAddress((void**)&e1r, g_e1r);
    cudaGetSymbolAddress((void**)&wqr, g_wqr);
    cudaGetSymbolAddress((void**)&wcr, g_wcr);

    cudaFuncSetAttribute(gemm_tf32_kernel<false, false, true, false>,
                         cudaFuncAttributeMaxDynamicSharedMemorySize, GEMM_SMEM_BYTES);
    cudaFuncSetAttribute(gemm_tf32_kernel<true, false, false, true>,
                         cudaFuncAttributeMaxDynamicSharedMemorySize, GEMM_SMEM_BYTES);
    cudaFuncSetAttribute(gemm_tf32_kernel<true, false, false, false>,
                         cudaFuncAttributeMaxDynamicSharedMemorySize, GEMM_SMEM_BYTES);
    cudaFuncSetAttribute(gemm_tf32_kernel<true, true, false, false>,
                         cudaFuncAttributeMaxDynamicSharedMemorySize, GEMM_SMEM_BYTES);

    const long long headSlab = (long long)S_DIM * 512;
    const float invSqrtQ = 0.044194173824159216f;  // 1/sqrt(512)

    // ---- pre-round inputs to tf32 (removes per-fragment conversion in GEMMs) ----
    {
        const int T = 256;
        int n4;
        n4 = (S_DIM * X_DIM) / 4;
        round_tf32_kernel<<<(n4 + T - 1) / T, T>>>(x, xr, n4);
        n4 = (Q_DIM * S_DIM) / 4;
        round_tf32_kernel<<<(n4 + T - 1) / T, T>>>(enc0, e0r, n4);
        n4 = (ZV_DIM * S_DIM) / 4;
        round_tf32_kernel<<<(n4 + T - 1) / T, T>>>(enc1, e1r, n4);
        n4 = (H_DIM * Q_DIM * X_DIM) / 4;
        round_tf32_kernel<<<(n4 + T - 1) / T, T>>>(Wq, wqr, n4);
        n4 = (ZV_DIM * H_DIM * ZV_DIM) / 4;
        round_tf32_kernel<<<(n4 + T - 1) / T, T>>>(Wc, wcr, n4);
    }

    // zero k, v (split-K atomics accumulate into them)
    zero_kernel<<<(512 * 512 + 255) / 256, 256>>>(kbuf, 512 * 512);
    zero_kernel<<<(512 * 512 + 255) / 256, 256>>>(vbuf, 512 * 512);

    // k = enc0 @ x ; v = enc1 @ x   (M=N=512, K=8192, split-K=16)
    {
        dim3 g(512 / BN, 512 / BM, 16);
        gemm_tf32_kernel<false, false, true, false><<<g, 256, GEMM_SMEM_BYTES>>>(
            e0r, xr, kbuf, nullptr, 1.0f, 512, 512, 8192, 8192, 512, 512,
            0, 0, 0, 0, 0);
        gemm_tf32_kernel<false, false, true, false><<<g, 256, GEMM_SMEM_BYTES>>>(
            e1r, xr, vbuf, nullptr, 1.0f, 512, 512, 8192, 8192, 512, 512,
            0, 0, 0, 0, 0);
    }
    // round k, v in place (they feed later GEMMs as tf32 operands)
    {
        const int n4 = (512 * 512) / 4;
        round_tf32_kernel<<<(n4 + 255) / 256, 256>>>(kbuf, kbuf, n4);
        round_tf32_kernel<<<(n4 + 255) / 256, 256>>>(vbuf, vbuf, n4);
    }

    dim3 gbig(512 / BN, S_DIM / BM, H_DIM);  // (4, 64, 8)

    // q' = (x @ Wq[h]^T + bq[h]) * 1/sqrt(Q)  -> bufA  (rounded at epilogue)
    gemm_tf32_kernel<true, false, false, true><<<gbig, 256, GEMM_SMEM_BYTES>>>(
        xr, wqr, bufA, bq, invSqrtQ, S_DIM, 512, 512, 512, 512, 512,
        0, 512LL * 512, headSlab, 512, 0);

    // e = q' @ k^T  -> bufB
    gemm_tf32_kernel<true, false, false, false><<<gbig, 256, GEMM_SMEM_BYTES>>>(
        bufA, kbuf, bufB, nullptr, 1.0f, S_DIM, 512, 512, 512, 512, 512,
        headSlab, 0, headSlab, 0, 0);

    // softmax rows (H*S rows of 512), in place, tf32-rounded output
    softmax512_kernel<<<(H_DIM * S_DIM) / 8, dim3(32, 8)>>>(bufB, H_DIM * S_DIM);

    // z = e @ v^T  -> bufA  (rounded at epilogue)
    gemm_tf32_kernel<true, false, false, true><<<gbig, 256, GEMM_SMEM_BYTES>>>(
        bufB, vbuf, bufA, nullptr, 1.0f, S_DIM, 512, 512, 512, 512, 512,
        headSlab, 0, headSlab, 0, 0);

    // out = super_z @ Wc^T + bc   (A head-interleaved: col c -> z[c>>9][s][c&511])
    {
        dim3 g(512 / BN, S_DIM / BM, 1);
        gemm_tf32_kernel<true, true, false, false><<<g, 256, GEMM_SMEM_BYTES>>>(
            bufA, wcr, out, bc, 1.0f, S_DIM, 512, H_DIM * 512, 512, H_DIM * 512, 512,
            0, 0, 0, 0, headSlab);
    }
}

// round 8
// speedup vs baseline: 6.2826x; 5.9573x over previous
#include <cuda_runtime.h>
#include <cuda_fp16.h>
#include <mma.h>
#include <cstdint>

using namespace nvcuda;

// Problem constants
#define S_DIM 8192
#define X_DIM 512
#define Q_DIM 512
#define ZV_DIM 512
#define H_DIM 8

// Scratch (device globals: allocation-free)
__device__ float g_k[512 * 512];   // split-K fp32 accumulators
__device__ float g_v[512 * 512];
// fp16 operand copies
__device__ __half g_xh[(size_t)S_DIM * X_DIM];
__device__ __half g_e0h[(size_t)Q_DIM * S_DIM];
__device__ __half g_e1h[(size_t)ZV_DIM * S_DIM];
__device__ __half g_wqh[(size_t)H_DIM * Q_DIM * X_DIM];
__device__ __half g_wch[(size_t)ZV_DIM * H_DIM * ZV_DIM];
__device__ __half g_kh[512 * 512];
__device__ __half g_vh[512 * 512];
// fp16 intermediates
__device__ __half g_qh[(size_t)H_DIM * S_DIM * 512];
__device__ __half g_eh[(size_t)H_DIM * S_DIM * 512];
__device__ __half g_zh[(size_t)H_DIM * S_DIM * 512];

// ---------------- cp.async helpers ----------------
__device__ __forceinline__ void cp_async16(void* smem_ptr, const void* gptr) {
    unsigned int saddr = (unsigned int)__cvta_generic_to_shared(smem_ptr);
    asm volatile("cp.async.cg.shared.global [%0], [%1], 16;\n" ::"r"(saddr), "l"(gptr));
}
__device__ __forceinline__ void cp_commit() {
    asm volatile("cp.async.commit_group;\n" ::);
}
template <int N>
__device__ __forceinline__ void cp_wait() {
    asm volatile("cp.async.wait_group %0;\n" ::"n"(N));
}

// ------------- GEMM: fp16 wmma 16x16x16, 128x128x64 tile, 8 warps, 2-stage cp.async ---
constexpr int BM = 128, BN = 128, BK = 64;
constexpr int LDA_S = BK + 8;     // 72 halves : As[BM][LDA_S]
constexpr int LDBT_S = BK + 8;    // 72 halves : Bst[BN][LDBT_S] (B row-major [N][K])
constexpr int LDBN_S = BN + 8;    // 136 halves: Bs[BK][LDBN_S]  (B row-major [K][N])
constexpr int LDC_S = BN + 8;     // 136 floats: Cs[BM][LDC_S]
constexpr int STAGE_H = BM * LDA_S + BN * LDBT_S;      // 18432 halves = 36864 B / stage
constexpr int GEMM_SMEM_BYTES = 2 * STAGE_H * 2;       // 73728 (>= epilogue 69632)

template <bool BTRANS, bool AHEADED, bool ATOMIC, bool OUTH>
__global__ __launch_bounds__(256)
void gemm_f16_kernel(const __half* __restrict__ A, const __half* __restrict__ B,
                     void* __restrict__ Cv, const float* __restrict__ bias,
                     float alpha, int M, int N, int K,
                     int lda, int ldb, int ldc,
                     long long strideA, long long strideB, long long strideC,
                     long long strideBias, long long headSlab) {
    extern __shared__ __half smemh[];

    const int z = blockIdx.z;
    int kBegin = 0, kCount = K;
    if constexpr (ATOMIC) {
        kCount = K / gridDim.z;
        kBegin = z * kCount;
    } else {
        A += z * strideA;
        B += z * strideB;
        if (bias) bias += z * strideBias;
    }
    const int mBase = blockIdx.y * BM;
    const int nBase = blockIdx.x * BN;

    const int tid = threadIdx.x;
    const int warp = tid >> 5;
    const int wm = warp >> 1;  // 0..3 (32-row strip)
    const int wn = warp & 1;   // 0..1 (64-col strip)

    wmma::fragment<wmma::accumulator, 16, 16, 16, float> acc[2][4];
#pragma unroll
    for (int i = 0; i < 2; ++i)
#pragma unroll
        for (int j = 0; j < 4; ++j) wmma::fill_fragment(acc[i][j], 0.0f);

    // ---- async stage loader (16B = 8 halves per cp.async) ----
    auto load_stage = [&](int kc, int stage) {
        __half* As = smemh + stage * STAGE_H;
        __half* Bs = As + BM * LDA_S;
        const int kcol = kBegin + kc * BK;
        // A tile: 128 rows x 64 halves -> 1024 chunks of 8 halves
#pragma unroll
        for (int it = 0; it < 4; ++it) {
            const int idx = tid + it * 256;
            const int r = idx >> 3;   // 0..127
            const int c8 = idx & 7;   // chunk of 8 halves
            const __half* src;
            if constexpr (AHEADED) {
                src = A + (long long)(kcol >> 9) * headSlab +
                      (long long)(mBase + r) * 512 + (kcol & 511) + c8 * 8;
            } else {
                src = A + (long long)(mBase + r) * lda + kcol + c8 * 8;
            }
            cp_async16(&As[r * LDA_S + c8 * 8], src);
        }
        if constexpr (BTRANS) {
            // B tile: 128 n-rows x 64 k-halves
#pragma unroll
            for (int it = 0; it < 4; ++it) {
                const int idx = tid + it * 256;
                const int n = idx >> 3;
                const int c8 = idx & 7;
                cp_async16(&Bs[n * LDBT_S + c8 * 8],
                           B + (long long)(nBase + n) * ldb + kcol + c8 * 8);
            }
        } else {
            // B tile: 64 k-rows x 128 n-halves -> 16 chunks/row
#pragma unroll
            for (int it = 0; it < 4; ++it) {
                const int idx = tid + it * 256;
                const int r = idx >> 4;   // 0..63
                const int c8 = idx & 15;  // 0..15
                cp_async16(&Bs[r * LDBN_S + c8 * 8],
                           B + (long long)(kcol + r) * ldb + nBase + c8 * 8);
            }
        }
    };

    const int nChunks = kCount / BK;

    load_stage(0, 0);
    cp_commit();

    for (int kc = 0; kc < nChunks; ++kc) {
        cp_wait<0>();
        __syncthreads();
        if (kc + 1 < nChunks) {
            load_stage(kc + 1, (kc + 1) & 1);
            cp_commit();
        }
        const __half* As = smemh + (kc & 1) * STAGE_H;
        const __half* Bs = As + BM * LDA_S;

#pragma unroll
        for (int kk = 0; kk < BK / 16; ++kk) {
            wmma::fragment<wmma::matrix_a, 16, 16, 16, __half, wmma::row_major> af[2];
#pragma unroll
            for (int i = 0; i < 2; ++i)
                wmma::load_matrix_sync(af[i],
                                       &As[(wm * 32 + i * 16) * LDA_S + kk * 16], LDA_S);
#pragma unroll
            for (int j = 0; j < 4; ++j) {
                if constexpr (BTRANS) {
                    wmma::fragment<wmma::matrix_b, 16, 16, 16, __half,
                                   wmma::col_major> bf;
                    wmma::load_matrix_sync(
                        bf, &Bs[(wn * 64 + j * 16) * LDBT_S + kk * 16], LDBT_S);
#pragma unroll
                    for (int i = 0; i < 2; ++i)
                        wmma::mma_sync(acc[i][j], af[i], bf, acc[i][j]);
                } else {
                    wmma::fragment<wmma::matrix_b, 16, 16, 16, __half,
                                   wmma::row_major> bf;
                    wmma::load_matrix_sync(
                        bf, &Bs[(kk * 16) * LDBN_S + wn * 64 + j * 16], LDBN_S);
#pragma unroll
                    for (int i = 0; i < 2; ++i)
                        wmma::mma_sync(acc[i][j], af[i], bf, acc[i][j]);
                }
            }
        }
    }
    __syncthreads();  // stage buffers free for epilogue reuse

    // ---- epilogue: accum -> smem (fp32) -> coalesced global stores ----
    float* Cs = reinterpret_cast<float*>(smemh);  // [BM][LDC_S]
#pragma unroll
    for (int i = 0; i < 2; ++i)
#pragma unroll
        for (int j = 0; j < 4; ++j)
            wmma::store_matrix_sync(&Cs[(wm * 32 + i * 16) * LDC_S + wn * 64 + j * 16],
                                    acc[i][j], LDC_S, wmma::mem_row_major);
    __syncthreads();

#pragma unroll
    for (int it = 0; it < 16; ++it) {
        const int idx = tid + it * 256;  // 0..4095
        const int r = idx >> 5;          // 0..127
        const int c4 = idx & 31;         // 0..31 (4-wide columns)
        float4 v = *reinterpret_cast<float4*>(&Cs[r * LDC_S + c4 * 4]);
        const int ncol = nBase + c4 * 4;
        if constexpr (ATOMIC) {
            float* dst = reinterpret_cast<float*>(Cv) + (long long)(mBase + r) * ldc + ncol;
            atomicAdd(dst + 0, v.x);
            atomicAdd(dst + 1, v.y);
            atomicAdd(dst + 2, v.z);
            atomicAdd(dst + 3, v.w);
        } else {
            if (bias != nullptr) {
                v.x += bias[ncol + 0];
                v.y += bias[ncol + 1];
                v.z += bias[ncol + 2];
                v.w += bias[ncol + 3];
            }
            v.x *= alpha; v.y *= alpha; v.z *= alpha; v.w *= alpha;
            if constexpr (OUTH) {
                __half* dst = reinterpret_cast<__half*>(Cv) + z * strideC +
                              (long long)(mBase + r) * ldc + ncol;
                __half2 h0 = __floats2half2_rn(v.x, v.y);
                __half2 h1 = __floats2half2_rn(v.z, v.w);
                *reinterpret_cast<__half2*>(dst) = h0;
                *reinterpret_cast<__half2*>(dst + 2) = h1;
            } else {
                float* dst = reinterpret_cast<float*>(Cv) + z * strideC +
                             (long long)(mBase + r) * ldc + ncol;
                *reinterpret_cast<float4*>(dst) = v;
            }
        }
    }
}

// ---------------- softmax over half rows of 512 (1 warp per row) ----------------
__global__ void softmax512_half_kernel(__half* __restrict__ data, int rows) {
    const int row = blockIdx.x * blockDim.y + threadIdx.y;
    if (row >= rows) return;
    __half* p = data + (long long)row * 512;
    const int lane = threadIdx.x;
    uint4* p16 = reinterpret_cast<uint4*>(p);  // 64 x 16B chunks (8 halves each)

    uint4 u[2];
    float f[16];
#pragma unroll
    for (int i = 0; i < 2; ++i) u[i] = p16[lane + i * 32];
#pragma unroll
    for (int i = 0; i < 2; ++i) {
        const __half2* h2 = reinterpret_cast<const __half2*>(&u[i]);
#pragma unroll
        for (int j = 0; j < 4; ++j) {
            float2 fv = __half22float2(h2[j]);
            f[i * 8 + j * 2 + 0] = fv.x;
            f[i * 8 + j * 2 + 1] = fv.y;
        }
    }
    float mx = -3.0e38f;
#pragma unroll
    for (int i = 0; i < 16; ++i) mx = fmaxf(mx, f[i]);
#pragma unroll
    for (int o = 16; o; o >>= 1) mx = fmaxf(mx, __shfl_xor_sync(0xffffffffu, mx, o));
    float sum = 0.0f;
#pragma unroll
    for (int i = 0; i < 16; ++i) {
        f[i] = __expf(f[i] - mx);
        sum += f[i];
    }
#pragma unroll
    for (int o = 16; o; o >>= 1) sum += __shfl_xor_sync(0xffffffffu, sum, o);
    const float inv = 1.0f / sum;
#pragma unroll
    for (int i = 0; i < 2; ++i) {
        __half2* h2 = reinterpret_cast<__half2*>(&u[i]);
#pragma unroll
        for (int j = 0; j < 4; ++j)
            h2[j] = __floats2half2_rn(f[i * 8 + j * 2] * inv, f[i * 8 + j * 2 + 1] * inv);
        p16[lane + i * 32] = u[i];
    }
}

__global__ void zero_kernel(float* __restrict__ p, int n) {
    const int i = blockIdx.x * blockDim.x + threadIdx.x;
    if (i < n) p[i] = 0.0f;
}

// float4 -> 2x half2 convert-copy
__global__ void f2h_kernel(const float* __restrict__ in, __half* __restrict__ out,
                           int n4) {
    const int i = blockIdx.x * blockDim.x + threadIdx.x;
    if (i < n4) {
        float4 v = reinterpret_cast<const float4*>(in)[i];
        __half2* o2 = reinterpret_cast<__half2*>(out) + 2 * i;
        o2[0] = __floats2half2_rn(v.x, v.y);
        o2[1] = __floats2half2_rn(v.z, v.w);
    }
}

// ---------------- launcher ----------------
extern "C" void kernel_launch(void* const* d_in, const int* in_sizes, int n_in,
                              void* d_out, int out_size) {
    const float* x    = (const float*)d_in[0];  // [S, X]
    const float* enc0 = (const float*)d_in[1];  // [Q, S]
    const float* enc1 = (const float*)d_in[2];  // [ZV, S]
    const float* Wq   = (const float*)d_in[3];  // [H, Q, X]
    const float* bq   = (const float*)d_in[4];  // [H, Q]
    const float* Wc   = (const float*)d_in[5];  // [ZV, H*ZV]
    const float* bc   = (const float*)d_in[6];  // [ZV]
    float* out = (float*)d_out;                 // [S, ZV]

    float *kbuf, *vbuf;
    __half *xh, *e0h, *e1h, *wqh, *wch, *kh, *vh, *qh, *eh, *zh;
    cudaGetSymbolAddress((void**)&kbuf, g_k);
    cudaGetSymbolAddress((void**)&vbuf, g_v);
    cudaGetSymbolAddress((void**)&xh, g_xh);
    cudaGetSymbolAddress((void**)&e0h, g_e0h);
    cudaGetSymbolAddress((void**)&e1h, g_e1h);
    cudaGetSymbolAddress((void**)&wqh, g_wqh);
    cudaGetSymbolAddress((void**)&wch, g_wch);
    cudaGetSymbolAddress((void**)&kh, g_kh);
    cudaGetSymbolAddress((void**)&vh, g_vh);
    cudaGetSymbolAddress((void**)&qh, g_qh);
    cudaGetSymbolAddress((void**)&eh, g_eh);
    cudaGetSymbolAddress((void**)&zh, g_zh);

    cudaFuncSetAttribute(gemm_f16_kernel<false, false, true, false>,
                         cudaFuncAttributeMaxDynamicSharedMemorySize, GEMM_SMEM_BYTES);
    cudaFuncSetAttribute(gemm_f16_kernel<true, false, false, true>,
                         cudaFuncAttributeMaxDynamicSharedMemorySize, GEMM_SMEM_BYTES);
    cudaFuncSetAttribute(gemm_f16_kernel<true, true, false, false>,
                         cudaFuncAttributeMaxDynamicSharedMemorySize, GEMM_SMEM_BYTES);

    const long long headSlab = (long long)S_DIM * 512;
    const float invSqrtQ = 0.044194173824159216f;  // 1/sqrt(512)
    const int T = 256;

    // ---- convert inputs to fp16 ----
    {
        int n4;
        n4 = (S_DIM * X_DIM) / 4;
        f2h_kernel<<<(n4 + T - 1) / T, T>>>(x, xh, n4);
        n4 = (Q_DIM * S_DIM) / 4;
        f2h_kernel<<<(n4 + T - 1) / T, T>>>(enc0, e0h, n4);
        n4 = (ZV_DIM * S_DIM) / 4;
        f2h_kernel<<<(n4 + T - 1) / T, T>>>(enc1, e1h, n4);
        n4 = (H_DIM * Q_DIM * X_DIM) / 4;
        f2h_kernel<<<(n4 + T - 1) / T, T>>>(Wq, wqh, n4);
        n4 = (ZV_DIM * H_DIM * ZV_DIM) / 4;
        f2h_kernel<<<(n4 + T - 1) / T, T>>>(Wc, wch, n4);
    }

    // zero k, v fp32 accumulators
    zero_kernel<<<(512 * 512 + T - 1) / T, T>>>(kbuf, 512 * 512);
    zero_kernel<<<(512 * 512 + T - 1) / T, T>>>(vbuf, 512 * 512);

    // k = enc0 @ x ; v = enc1 @ x   (M=N=512, K=8192, split-K=16, fp32 atomics)
    {
        dim3 g(512 / BN, 512 / BM, 16);
        gemm_f16_kernel<false, false, true, false><<<g, 256, GEMM_SMEM_BYTES>>>(
            e0h, xh, kbuf, nullptr, 1.0f, 512, 512, 8192, 8192, 512, 512,
            0, 0, 0, 0, 0);
        gemm_f16_kernel<false, false, true, false><<<g, 256, GEMM_SMEM_BYTES>>>(
            e1h, xh, vbuf, nullptr, 1.0f, 512, 512, 8192, 8192, 512, 512,
            0, 0, 0, 0, 0);
    }
    // convert k, v to fp16 operands
    {
        const int n4 = (512 * 512) / 4;
        f2h_kernel<<<(n4 + T - 1) / T, T>>>(kbuf, kh, n4);
        f2h_kernel<<<(n4 + T - 1) / T, T>>>(vbuf, vh, n4);
    }

    dim3 gbig(512 / BN, S_DIM / BM, H_DIM);  // (4, 64, 8)

    // q' = (x @ Wq[h]^T + bq[h]) * 1/sqrt(Q)  -> qh (fp16)
    gemm_f16_kernel<true, false, false, true><<<gbig, 256, GEMM_SMEM_BYTES>>>(
        xh, wqh, qh, bq, invSqrtQ, S_DIM, 512, 512, 512, 512, 512,
        0, 512LL * 512, headSlab, 512, 0);

    // e = q' @ k^T  -> eh (fp16 logits)
    gemm_f16_kernel<true, false, false, true><<<gbig, 256, GEMM_SMEM_BYTES>>>(
        qh, kh, eh, nullptr, 1.0f, S_DIM, 512, 512, 512, 512, 512,
        headSlab, 0, headSlab, 0, 0);

    // softmax rows (H*S rows of 512), in place on fp16
    softmax512_half_kernel<<<(H_DIM * S_DIM) / 8, dim3(32, 8)>>>(eh, H_DIM * S_DIM);

    // z = e @ v^T  -> zh (fp16)
    gemm_f16_kernel<true, false, false, true><<<gbig, 256, GEMM_SMEM_BYTES>>>(
        eh, vh, zh, nullptr, 1.0f, S_DIM, 512, 512, 512, 512, 512,
        headSlab, 0, headSlab, 0, 0);

    // out = super_z @ Wc^T + bc   (A head-interleaved: col c -> z[c>>9][s][c&511])
    {
        dim3 g(512 / BN, S_DIM / BM, 1);
        gemm_f16_kernel<true, true, false, false><<<g, 256, GEMM_SMEM_BYTES>>>(
            zh, wch, out, bc, 1.0f, S_DIM, 512, H_DIM * 512, 512, H_DIM * 512, 512,
            0, 0, 0, 0, headSlab);
    }
}